// round 13
// baseline (speedup 1.0000x reference)
#include <cuda_runtime.h>
#include <cuda_bf16.h>
#include <math.h>
#include <stdint.h>

// ---------------- problem constants ----------------------------------------
#define T_TOK 4096
#define D_DIM 1024
#define E_NUM 8
#define W_DIM 1024
#define CAP   4096          // per-expert slot capacity (overflow-proof)
#define K3    3072          // weights/x: A=[hi|hi|lo], B=[hi|lo|hi] concatenated
#define K2    2048          // activations: [hi|lo] stored, chunk-remapped on read
#define BK    32
#define NCH   (K3 / BK)     // 96
#define SAS   40            // smem row stride (bf16) -> conflict-free frag LDS
#define BM    128
#define BN    256

// dynamic smem layout (bytes)
#define A_ST  (BM * SAS * 2)                 // 10240 per stage
#define B_ST  (BN * SAS * 2)                 // 20480 per stage
#define A_OFF(s) ((s) * A_ST)                // 0, 10240
#define B_OFF(s) (2 * A_ST + (s) * B_ST)     // 20480, 40960
#define TOK_OFF  (2 * A_ST + 2 * B_ST)       // 61440
#define WT_OFF   (TOK_OFF + 512)
#define SM_BYTES (TOK_OFF + 1024)            // 62464

// ---------------- device scratch --------------------------------------------
__device__ int   g_fill[E_NUM];
__device__ int   g_tok [E_NUM * CAP];
__device__ float g_wt  [E_NUM * CAP];
__device__ __nv_bfloat16 g_xcat [(size_t)T_TOK * K3];           // 25 MB
__device__ __nv_bfloat16 g_w1cat[(size_t)E_NUM * W_DIM * K3];   // 50 MB [e][n][k]
__device__ __nv_bfloat16 g_w2cat[(size_t)E_NUM * D_DIM * K3];   // 50 MB [e][d][k]
__device__ __nv_bfloat16 g_acat [(size_t)E_NUM * CAP * K2];     // 134 MB [slot][hi|lo]

// chunk -> stored-K offset for the deduped activation buffer ([hi|hi|lo] read)
__device__ __forceinline__ int kbA2(int c) {
    return (c < 32) ? c * 32 : (c < 64 ? (c - 32) * 32 : c * 32 - 1024);
}

// ---------------- pre-pass ---------------------------------------------------
__global__ void zcnt_kernel() {
    if (threadIdx.x < E_NUM) g_fill[threadIdx.x] = 0;
}

// fused: zero out + x split + router + slot assignment
__global__ void __launch_bounds__(128) pre_x(const float* __restrict__ x,
                                             const float* __restrict__ rw,
                                             float* __restrict__ out) {
    __shared__ float wsum[4][E_NUM];
    int t = blockIdx.x;
    int tid = threadIdx.x, lane = tid & 31, wrp = tid >> 5;
    const float* xr = x + (size_t)t * D_DIM;
    int d0 = tid * 8;

    float4 v0 = *(const float4*)(xr + d0);
    float4 v1 = *(const float4*)(xr + d0 + 4);
    float xv[8] = { v0.x, v0.y, v0.z, v0.w, v1.x, v1.y, v1.z, v1.w };

    float4 z = make_float4(0.f, 0.f, 0.f, 0.f);
    *(float4*)(out + (size_t)t * D_DIM + d0)     = z;
    *(float4*)(out + (size_t)t * D_DIM + d0 + 4) = z;

    size_t b = (size_t)t * K3;
    __nv_bfloat16 hi8[8], lo8[8];
#pragma unroll
    for (int i = 0; i < 8; i++) {
        hi8[i] = __float2bfloat16(xv[i]);
        lo8[i] = __float2bfloat16(xv[i] - __bfloat162float(hi8[i]));
    }
    *(uint4*)(&g_xcat[b + d0])        = *(uint4*)hi8;
    *(uint4*)(&g_xcat[b + 1024 + d0]) = *(uint4*)hi8;
    *(uint4*)(&g_xcat[b + 2048 + d0]) = *(uint4*)lo8;

    float p[E_NUM];
#pragma unroll
    for (int e = 0; e < E_NUM; e++) {
        const float* wr = rw + e * D_DIM + d0;
        float s = 0.f;
#pragma unroll
        for (int i = 0; i < 8; i++) s += xv[i] * wr[i];
        p[e] = s;
    }
#pragma unroll
    for (int e = 0; e < E_NUM; e++)
#pragma unroll
        for (int o = 16; o; o >>= 1) p[e] += __shfl_xor_sync(0xffffffffu, p[e], o);
    if (lane == 0)
#pragma unroll
        for (int e = 0; e < E_NUM; e++) wsum[wrp][e] = p[e];
    __syncthreads();
    if (tid == 0) {
        float q[E_NUM];
#pragma unroll
        for (int e = 0; e < E_NUM; e++)
            q[e] = wsum[0][e] + wsum[1][e] + wsum[2][e] + wsum[3][e];
        int i1 = 0; float v1 = q[0];
#pragma unroll
        for (int e = 1; e < E_NUM; e++) if (q[e] > v1) { v1 = q[e]; i1 = e; }
        int i2 = -1; float v2 = -3.0e38f;
#pragma unroll
        for (int e = 0; e < E_NUM; e++) if (e != i1 && q[e] > v2) { v2 = q[e]; i2 = e; }
        float p1 = 1.0f / (1.0f + expf(-v1));
        float p2 = 1.0f / (1.0f + expf(-v2));
        float s = p1 + p2 + 1e-20f;
        int pos1 = atomicAdd(&g_fill[i1], 1);
        g_tok[i1 * CAP + pos1] = t;
        g_wt [i1 * CAP + pos1] = p1 / s;
        int pos2 = atomicAdd(&g_fill[i2], 1);
        g_tok[i2 * CAP + pos2] = t;
        g_wt [i2 * CAP + pos2] = p2 / s;
    }
}

// Per-expert 1024x1024 transpose + split: dst[e][n][k-seg], segs [hi|lo|hi]
__global__ void convert_w(const float* __restrict__ w1, const float* __restrict__ w2) {
    __shared__ float tile[32][33];
    int sel = blockIdx.z >> 3;
    int e   = blockIdx.z & 7;
    int r0 = blockIdx.y * 32, c0 = blockIdx.x * 32;
    const float* src = sel ? w2 : w1;
    int src_ld  = sel ? 1024 : 8192;
    int row_off = sel ? e * 1024 : 0;
    int col_off = sel ? 0 : e * 1024;
    const float* s = src + (size_t)(row_off + r0) * src_ld + col_off + c0;
#pragma unroll
    for (int i = threadIdx.y; i < 32; i += 8)
        tile[i][threadIdx.x] = s[(size_t)i * src_ld + threadIdx.x];
    __syncthreads();
    __nv_bfloat16* d = (sel ? g_w2cat : g_w1cat) + (size_t)e * 1024 * K3;
#pragma unroll
    for (int i = threadIdx.y; i < 32; i += 8) {
        int c = c0 + i;
        int r = r0 + threadIdx.x;
        float v = tile[threadIdx.x][i];
        __nv_bfloat16 hi = __float2bfloat16(v);
        __nv_bfloat16 lo = __float2bfloat16(v - __bfloat162float(hi));
        size_t bi = (size_t)c * K3 + r;
        d[bi] = hi; d[bi + 1024] = lo; d[bi + 2048] = hi;
    }
}

// ---------------- mma.sync helper -------------------------------------------
__device__ __forceinline__ void mma16816(float* d, const uint32_t* a, const uint32_t* b) {
    asm volatile(
        "mma.sync.aligned.m16n8k16.row.col.f32.bf16.bf16.f32 "
        "{%0,%1,%2,%3}, {%4,%5,%6,%7}, {%8,%9}, {%0,%1,%2,%3};"
        : "+f"(d[0]), "+f"(d[1]), "+f"(d[2]), "+f"(d[3])
        : "r"(a[0]), "r"(a[1]), "r"(a[2]), "r"(a[3]), "r"(b[0]), "r"(b[1]));
}

// ---------------- grouped GEMM: 128x256 CTA tile, 64x64 warp tiles ----------
// MODE 0: up-proj  (A = g_xcat [K3] by token, B = g_w1cat, epi -> g_acat [hi|lo])
// MODE 1: down-proj(A = g_acat [K2] chunk-remapped, B = g_w2cat, epi -> atomicAdd)
template <int MODE>
__global__ void __launch_bounds__(256) moe_gemm(float* __restrict__ out) {
    extern __shared__ char sm[];
    int*   tok_s = (int*)  (sm + TOK_OFF);
    float* wt_s  = (float*)(sm + WT_OFF);

    int e = blockIdx.z;
    int cnt = g_fill[e];
    int m0 = blockIdx.y * BM;
    if (m0 >= cnt) return;
    int base = e * CAP;
    int n0 = blockIdx.x * BN;

    int tid = threadIdx.x, lane = tid & 31, wid = tid >> 5;
    int wm = wid & 1, wn = wid >> 1;        // warps 2 x 4 -> 64 x 64 tile per warp
    int g = lane >> 2, tig = lane & 3;

    if (tid < 128) {
        int m = m0 + tid;
        tok_s[tid] = (m < cnt) ? g_tok[base + m] : 0;
        wt_s [tid] = (m < cnt) ? g_wt [base + m] : 0.0f;
    }
    __syncthreads();

    // global load assignment: A 512 uint4 (2/thread), B 1024 uint4 (4/thread)
    int arow = tid >> 2;                    // 0..63
    int aseg = (tid & 3) * 8;
    const __nv_bfloat16 *Ab0, *Ab1;
    if (MODE == 0) {
        Ab0 = g_xcat + (size_t)tok_s[arow] * K3 + aseg;
        Ab1 = g_xcat + (size_t)tok_s[arow + 64] * K3 + aseg;
    } else {
        Ab0 = g_acat + (size_t)(base + m0 + arow) * K2 + aseg;
        Ab1 = g_acat + (size_t)(base + m0 + arow + 64) * K2 + aseg;
    }
    const __nv_bfloat16* Bexp = (MODE ? g_w2cat : g_w1cat) + (size_t)e * 1024 * K3;
    const __nv_bfloat16* Bb[4];
#pragma unroll
    for (int i = 0; i < 4; i++)
        Bb[i] = Bexp + (size_t)(n0 + arow + i * 64) * K3 + aseg;

#define ASM(s, r, c) (*(__nv_bfloat16*)(sm + A_OFF(s) + ((r) * SAS + (c)) * 2))
#define BSM(s, r, c) (*(__nv_bfloat16*)(sm + B_OFF(s) + ((r) * SAS + (c)) * 2))

    float acc[4][8][4];
#pragma unroll
    for (int i = 0; i < 4; i++)
#pragma unroll
        for (int j = 0; j < 8; j++)
#pragma unroll
            for (int q = 0; q < 4; q++) acc[i][j][q] = 0.0f;

    // prologue: chunk 0 -> stage 0
    {
        uint4 a0 = *(const uint4*)(Ab0);
        uint4 a1 = *(const uint4*)(Ab1);
        *(uint4*)&ASM(0, arow,      aseg) = a0;
        *(uint4*)&ASM(0, arow + 64, aseg) = a1;
#pragma unroll
        for (int i = 0; i < 4; i++) {
            uint4 bv = *(const uint4*)(Bb[i]);
            *(uint4*)&BSM(0, arow + i * 64, aseg) = bv;
        }
    }
    __syncthreads();

#pragma unroll 1
    for (int c = 0; c < NCH; c++) {
        int s = c & 1;
        int d = s ^ 1;
        bool pf = (c + 1 < NCH);
        int kn  = (c + 1) * BK;
        int knA = (MODE == 1) ? kbA2(c + 1) : kn;

        // ---- A-prefetch ----
        uint4 pa0, pa1;
        if (pf) {
            pa0 = *(const uint4*)(Ab0 + knA);
            pa1 = *(const uint4*)(Ab1 + knA);
        }
        // ---- ks = 0 ----
        {
            const int kc = 0;
            uint32_t bfr[8][2];
#pragma unroll
            for (int nt = 0; nt < 8; nt++) {
                int rb = wn * 64 + nt * 8 + g;
                bfr[nt][0] = *(const uint32_t*)&BSM(s, rb, kc + tig * 2);
                bfr[nt][1] = *(const uint32_t*)&BSM(s, rb, kc + tig * 2 + 8);
            }
#pragma unroll
            for (int mt = 0; mt < 4; mt++) {
                uint32_t af[4];
                int r = wm * 64 + mt * 16 + g;
                af[0] = *(const uint32_t*)&ASM(s, r,     kc + tig * 2);
                af[1] = *(const uint32_t*)&ASM(s, r + 8, kc + tig * 2);
                af[2] = *(const uint32_t*)&ASM(s, r,     kc + tig * 2 + 8);
                af[3] = *(const uint32_t*)&ASM(s, r + 8, kc + tig * 2 + 8);
#pragma unroll
                for (int nt = 0; nt < 8; nt++)
                    mma16816(acc[mt][nt], af, bfr[nt]);
            }
        }
        // ---- store A-prefetch, fetch B-prefetch ----
        uint4 pb[4];
        if (pf) {
            *(uint4*)&ASM(d, arow,      aseg) = pa0;
            *(uint4*)&ASM(d, arow + 64, aseg) = pa1;
#pragma unroll
            for (int i = 0; i < 4; i++)
                pb[i] = *(const uint4*)(Bb[i] + kn);
        }
        // ---- ks = 1 ----
        {
            const int kc = 16;
            uint32_t bfr[8][2];
#pragma unroll
            for (int nt = 0; nt < 8; nt++) {
                int rb = wn * 64 + nt * 8 + g;
                bfr[nt][0] = *(const uint32_t*)&BSM(s, rb, kc + tig * 2);
                bfr[nt][1] = *(const uint32_t*)&BSM(s, rb, kc + tig * 2 + 8);
            }
#pragma unroll
            for (int mt = 0; mt < 4; mt++) {
                uint32_t af[4];
                int r = wm * 64 + mt * 16 + g;
                af[0] = *(const uint32_t*)&ASM(s, r,     kc + tig * 2);
                af[1] = *(const uint32_t*)&ASM(s, r + 8, kc + tig * 2);
                af[2] = *(const uint32_t*)&ASM(s, r,     kc + tig * 2 + 8);
                af[3] = *(const uint32_t*)&ASM(s, r + 8, kc + tig * 2 + 8);
#pragma unroll
                for (int nt = 0; nt < 8; nt++)
                    mma16816(acc[mt][nt], af, bfr[nt]);
            }
        }
        // ---- store B-prefetch ----
        if (pf) {
#pragma unroll
            for (int i = 0; i < 4; i++)
                *(uint4*)&BSM(d, arow + i * 64, aseg) = pb[i];
        }
        __syncthreads();
    }
#undef ASM
#undef BSM

    // ---------------- epilogue ----------------
#pragma unroll
    for (int mt = 0; mt < 4; mt++) {
#pragma unroll
        for (int half = 0; half < 2; half++) {
            int ml = wm * 64 + mt * 16 + g + half * 8;   // local row 0..127
            int m = m0 + ml;
            if (m >= cnt) continue;
            if (MODE == 0) {
                float wt = wt_s[ml];
                __nv_bfloat16* dst = g_acat + (size_t)(base + m) * K2;
#pragma unroll
                for (int nt = 0; nt < 8; nt++) {
                    int n = n0 + wn * 64 + nt * 8 + tig * 2;
                    float h0 = acc[mt][nt][half * 2 + 0];
                    float h1 = acc[mt][nt][half * 2 + 1];
                    float a0 = (h0 > 0.0f) ? wt * h0 * h0 : 0.0f;
                    float a1 = (h1 > 0.0f) ? wt * h1 * h1 : 0.0f;
                    __nv_bfloat16 hi0 = __float2bfloat16(a0);
                    __nv_bfloat16 hi1 = __float2bfloat16(a1);
                    __nv_bfloat16 lo0 = __float2bfloat16(a0 - __bfloat162float(hi0));
                    __nv_bfloat16 lo1 = __float2bfloat16(a1 - __bfloat162float(hi1));
                    __nv_bfloat162 hh; hh.x = hi0; hh.y = hi1;
                    __nv_bfloat162 ll; ll.x = lo0; ll.y = lo1;
                    *(__nv_bfloat162*)(dst + n)        = hh;
                    *(__nv_bfloat162*)(dst + 1024 + n) = ll;
                }
            } else {
                int tok = tok_s[ml];
                float* orow = out + (size_t)tok * D_DIM;
#pragma unroll
                for (int nt = 0; nt < 8; nt++) {
                    int n = n0 + wn * 64 + nt * 8 + tig * 2;
                    atomicAdd(&orow[n],     acc[mt][nt][half * 2 + 0]);
                    atomicAdd(&orow[n + 1], acc[mt][nt][half * 2 + 1]);
                }
            }
        }
    }
}

// ---------------- launch ------------------------------------------------------
extern "C" void kernel_launch(void* const* d_in, const int* in_sizes, int n_in,
                              void* d_out, int out_size) {
    const float* x  = (const float*)d_in[0];   // [2,2048,1024]
    const float* rw = (const float*)d_in[1];   // [8,1024]
    const float* w1 = (const float*)d_in[2];   // [1024, 8192]
    const float* w2 = (const float*)d_in[3];   // [8192, 1024]
    float* out = (float*)d_out;

    zcnt_kernel<<<1, 32>>>();
    pre_x<<<T_TOK, 128>>>(x, rw, out);

    dim3 tg(32, 32, 16), tb(32, 8);
    convert_w<<<tg, tb>>>(w1, w2);

    cudaFuncSetAttribute(moe_gemm<0>, cudaFuncAttributeMaxDynamicSharedMemorySize, SM_BYTES);
    cudaFuncSetAttribute(moe_gemm<1>, cudaFuncAttributeMaxDynamicSharedMemorySize, SM_BYTES);

    dim3 gup(W_DIM / BN, T_TOK / BM, E_NUM);   // (4, 32, 8)
    moe_gemm<0><<<gup, 256, SM_BYTES>>>(out);
    dim3 gdn(D_DIM / BN, T_TOK / BM, E_NUM);   // (4, 32, 8)
    moe_gemm<1><<<gdn, 256, SM_BYTES>>>(out);
}

// round 14
// speedup vs baseline: 1.2225x; 1.2225x over previous
#include <cuda_runtime.h>
#include <cuda_bf16.h>
#include <math.h>
#include <stdint.h>

// ---------------- problem constants ----------------------------------------
#define T_TOK 4096
#define D_DIM 1024
#define E_NUM 8
#define W_DIM 1024
#define CAP   4096          // per-expert slot capacity (overflow-proof)
#define K3    3072          // weights/x: A=[hi|hi|lo], B=[hi|lo|hi] concatenated
#define K2    2048          // activations: [hi|lo] stored, chunk-remapped on read
#define BK    64
#define NCH   (K3 / BK)     // 48
#define SAS   72            // smem row stride (bf16), BK=64 + pad (R9-validated)
#define BM    128
#define BN    128

// dynamic smem layout (bytes)
#define OP_ST    (128 * SAS * 2)             // 18432 per operand per stage
#define A_OFF(s) ((s) * OP_ST)               // 0, 18432
#define B_OFF(s) (2 * OP_ST + (s) * OP_ST)   // 36864, 55296
#define TOK_OFF  (4 * OP_ST)                 // 73728
#define WT_OFF   (TOK_OFF + 512)
#define SM_BYTES (TOK_OFF + 1024)            // 74752 (x2 CTAs = 149.5 KB < 228 KB)

// ---------------- device scratch --------------------------------------------
__device__ int   g_fill[E_NUM];
__device__ int   g_tok [E_NUM * CAP];
__device__ float g_wt  [E_NUM * CAP];
__device__ __nv_bfloat16 g_xcat [(size_t)T_TOK * K3];           // 25 MB
__device__ __nv_bfloat16 g_w1cat[(size_t)E_NUM * W_DIM * K3];   // 50 MB [e][n][k]
__device__ __nv_bfloat16 g_w2cat[(size_t)E_NUM * D_DIM * K3];   // 50 MB [e][d][k]
__device__ __nv_bfloat16 g_acat [(size_t)E_NUM * CAP * K2];     // 134 MB [slot][hi|lo]

// 64-wide chunk -> stored-K offset for deduped activations ([hi|hi|lo] read)
__device__ __forceinline__ int kbA64(int c) {
    return (c < 16) ? c * 64 : (c < 32 ? (c - 16) * 64 : (c - 32) * 64 + 1024);
}

// ---------------- pre-pass ---------------------------------------------------
__global__ void zcnt_kernel() {
    if (threadIdx.x < E_NUM) g_fill[threadIdx.x] = 0;
}

// fused: zero out + x split + router + slot assignment
__global__ void __launch_bounds__(128) pre_x(const float* __restrict__ x,
                                             const float* __restrict__ rw,
                                             float* __restrict__ out) {
    __shared__ float wsum[4][E_NUM];
    int t = blockIdx.x;
    int tid = threadIdx.x, lane = tid & 31, wrp = tid >> 5;
    const float* xr = x + (size_t)t * D_DIM;
    int d0 = tid * 8;

    float4 v0 = *(const float4*)(xr + d0);
    float4 v1 = *(const float4*)(xr + d0 + 4);
    float xv[8] = { v0.x, v0.y, v0.z, v0.w, v1.x, v1.y, v1.z, v1.w };

    float4 z = make_float4(0.f, 0.f, 0.f, 0.f);
    *(float4*)(out + (size_t)t * D_DIM + d0)     = z;
    *(float4*)(out + (size_t)t * D_DIM + d0 + 4) = z;

    size_t b = (size_t)t * K3;
    __nv_bfloat16 hi8[8], lo8[8];
#pragma unroll
    for (int i = 0; i < 8; i++) {
        hi8[i] = __float2bfloat16(xv[i]);
        lo8[i] = __float2bfloat16(xv[i] - __bfloat162float(hi8[i]));
    }
    *(uint4*)(&g_xcat[b + d0])        = *(uint4*)hi8;
    *(uint4*)(&g_xcat[b + 1024 + d0]) = *(uint4*)hi8;
    *(uint4*)(&g_xcat[b + 2048 + d0]) = *(uint4*)lo8;

    float p[E_NUM];
#pragma unroll
    for (int e = 0; e < E_NUM; e++) {
        const float* wr = rw + e * D_DIM + d0;
        float s = 0.f;
#pragma unroll
        for (int i = 0; i < 8; i++) s += xv[i] * wr[i];
        p[e] = s;
    }
#pragma unroll
    for (int e = 0; e < E_NUM; e++)
#pragma unroll
        for (int o = 16; o; o >>= 1) p[e] += __shfl_xor_sync(0xffffffffu, p[e], o);
    if (lane == 0)
#pragma unroll
        for (int e = 0; e < E_NUM; e++) wsum[wrp][e] = p[e];
    __syncthreads();
    if (tid == 0) {
        float q[E_NUM];
#pragma unroll
        for (int e = 0; e < E_NUM; e++)
            q[e] = wsum[0][e] + wsum[1][e] + wsum[2][e] + wsum[3][e];
        int i1 = 0; float v1 = q[0];
#pragma unroll
        for (int e = 1; e < E_NUM; e++) if (q[e] > v1) { v1 = q[e]; i1 = e; }
        int i2 = -1; float v2 = -3.0e38f;
#pragma unroll
        for (int e = 0; e < E_NUM; e++) if (e != i1 && q[e] > v2) { v2 = q[e]; i2 = e; }
        float p1 = 1.0f / (1.0f + expf(-v1));
        float p2 = 1.0f / (1.0f + expf(-v2));
        float s = p1 + p2 + 1e-20f;
        int pos1 = atomicAdd(&g_fill[i1], 1);
        g_tok[i1 * CAP + pos1] = t;
        g_wt [i1 * CAP + pos1] = p1 / s;
        int pos2 = atomicAdd(&g_fill[i2], 1);
        g_tok[i2 * CAP + pos2] = t;
        g_wt [i2 * CAP + pos2] = p2 / s;
    }
}

// Per-expert 1024x1024 transpose + split: dst[e][n][k-seg], segs [hi|lo|hi]
__global__ void convert_w(const float* __restrict__ w1, const float* __restrict__ w2) {
    __shared__ float tile[32][33];
    int sel = blockIdx.z >> 3;
    int e   = blockIdx.z & 7;
    int r0 = blockIdx.y * 32, c0 = blockIdx.x * 32;
    const float* src = sel ? w2 : w1;
    int src_ld  = sel ? 1024 : 8192;
    int row_off = sel ? e * 1024 : 0;
    int col_off = sel ? 0 : e * 1024;
    const float* s = src + (size_t)(row_off + r0) * src_ld + col_off + c0;
#pragma unroll
    for (int i = threadIdx.y; i < 32; i += 8)
        tile[i][threadIdx.x] = s[(size_t)i * src_ld + threadIdx.x];
    __syncthreads();
    __nv_bfloat16* d = (sel ? g_w2cat : g_w1cat) + (size_t)e * 1024 * K3;
#pragma unroll
    for (int i = threadIdx.y; i < 32; i += 8) {
        int c = c0 + i;
        int r = r0 + threadIdx.x;
        float v = tile[threadIdx.x][i];
        __nv_bfloat16 hi = __float2bfloat16(v);
        __nv_bfloat16 lo = __float2bfloat16(v - __bfloat162float(hi));
        size_t bi = (size_t)c * K3 + r;
        d[bi] = hi; d[bi + 1024] = lo; d[bi + 2048] = hi;
    }
}

// ---------------- mma.sync helper -------------------------------------------
__device__ __forceinline__ void mma16816(float* d, const uint32_t* a, const uint32_t* b) {
    asm volatile(
        "mma.sync.aligned.m16n8k16.row.col.f32.bf16.bf16.f32 "
        "{%0,%1,%2,%3}, {%4,%5,%6,%7}, {%8,%9}, {%0,%1,%2,%3};"
        : "+f"(d[0]), "+f"(d[1]), "+f"(d[2]), "+f"(d[3])
        : "r"(a[0]), "r"(a[1]), "r"(a[2]), "r"(a[3]), "r"(b[0]), "r"(b[1]));
}

// ---------------- grouped GEMM (BK=64, 4-phase prefetch, 2 CTA/SM) ----------
// MODE 0: up-proj  (A = g_xcat [K3] by token, B = g_w1cat, epi -> g_acat [hi|lo])
// MODE 1: down-proj(A = g_acat [K2] chunk-remapped, B = g_w2cat, epi -> atomicAdd)
template <int MODE>
__global__ void __launch_bounds__(256, 2) moe_gemm(float* __restrict__ out) {
    extern __shared__ char sm[];
    int*   tok_s = (int*)  (sm + TOK_OFF);
    float* wt_s  = (float*)(sm + WT_OFF);

    int e = blockIdx.z;
    int cnt = g_fill[e];
    int m0 = blockIdx.y * BM;
    if (m0 >= cnt) return;
    int base = e * CAP;
    int n0 = blockIdx.x * BN;

    int tid = threadIdx.x, lane = tid & 31, wid = tid >> 5;
    int wm = wid & 1, wn = wid >> 1;        // warps 2 x 4 -> 64 x 32 tile per warp
    int g = lane >> 2, tig = lane & 3;

    if (tid < 128) {
        int m = m0 + tid;
        tok_s[tid] = (m < cnt) ? g_tok[base + m] : 0;
        wt_s [tid] = (m < cnt) ? g_wt [base + m] : 0.0f;
    }
    __syncthreads();

    // global load assignment: rows arow0/arow0+64, segs aseg/aseg+32 (4 uint4 each op)
    int arow0 = tid >> 2, arow1 = arow0 + 64;
    int aseg  = (tid & 3) * 8;
    const __nv_bfloat16 *Ab0, *Ab1;
    if (MODE == 0) {
        Ab0 = g_xcat + (size_t)tok_s[arow0] * K3 + aseg;
        Ab1 = g_xcat + (size_t)tok_s[arow1] * K3 + aseg;
    } else {
        Ab0 = g_acat + (size_t)(base + m0 + arow0) * K2 + aseg;
        Ab1 = g_acat + (size_t)(base + m0 + arow1) * K2 + aseg;
    }
    const __nv_bfloat16* Bexp = (MODE ? g_w2cat : g_w1cat) + (size_t)e * 1024 * K3;
    const __nv_bfloat16* Bb0 = Bexp + (size_t)(n0 + arow0) * K3 + aseg;
    const __nv_bfloat16* Bb1 = Bexp + (size_t)(n0 + arow1) * K3 + aseg;

#define ASM(s, r, c) (*(__nv_bfloat16*)(sm + A_OFF(s) + ((r) * SAS + (c)) * 2))
#define BSM(s, r, c) (*(__nv_bfloat16*)(sm + B_OFF(s) + ((r) * SAS + (c)) * 2))

    float acc[4][4][4];
#pragma unroll
    for (int i = 0; i < 4; i++)
#pragma unroll
        for (int j = 0; j < 4; j++)
#pragma unroll
            for (int q = 0; q < 4; q++) acc[i][j][q] = 0.0f;

    // prologue: chunk 0 -> stage 0 (kbA64(0) = 0)
    {
        *(uint4*)&ASM(0, arow0, aseg)      = *(const uint4*)(Ab0);
        *(uint4*)&ASM(0, arow1, aseg)      = *(const uint4*)(Ab1);
        *(uint4*)&ASM(0, arow0, aseg + 32) = *(const uint4*)(Ab0 + 32);
        *(uint4*)&ASM(0, arow1, aseg + 32) = *(const uint4*)(Ab1 + 32);
        *(uint4*)&BSM(0, arow0, aseg)      = *(const uint4*)(Bb0);
        *(uint4*)&BSM(0, arow1, aseg)      = *(const uint4*)(Bb1);
        *(uint4*)&BSM(0, arow0, aseg + 32) = *(const uint4*)(Bb0 + 32);
        *(uint4*)&BSM(0, arow1, aseg + 32) = *(const uint4*)(Bb1 + 32);
    }
    __syncthreads();

#pragma unroll 1
    for (int c = 0; c < NCH; c++) {
        int s = c & 1;
        int d = s ^ 1;
        bool pf = (c + 1 < NCH);
        int knB = (c + 1) * BK;
        int knA = (MODE == 1) ? kbA64(c + 1) : knB;

        uint4 p0, p1;
        // ---- phase 0: fetch A seg0 ----
        if (pf) { p0 = *(const uint4*)(Ab0 + knA); p1 = *(const uint4*)(Ab1 + knA); }
        // ks 0
        {
            const int kc = 0;
            uint32_t bfr[4][2];
#pragma unroll
            for (int nt = 0; nt < 4; nt++) {
                int rb = wn * 32 + nt * 8 + g;
                bfr[nt][0] = *(const uint32_t*)&BSM(s, rb, kc + tig * 2);
                bfr[nt][1] = *(const uint32_t*)&BSM(s, rb, kc + tig * 2 + 8);
            }
#pragma unroll
            for (int mt = 0; mt < 4; mt++) {
                uint32_t af[4];
                int r = wm * 64 + mt * 16 + g;
                af[0] = *(const uint32_t*)&ASM(s, r,     kc + tig * 2);
                af[1] = *(const uint32_t*)&ASM(s, r + 8, kc + tig * 2);
                af[2] = *(const uint32_t*)&ASM(s, r,     kc + tig * 2 + 8);
                af[3] = *(const uint32_t*)&ASM(s, r + 8, kc + tig * 2 + 8);
#pragma unroll
                for (int nt = 0; nt < 4; nt++)
                    mma16816(acc[mt][nt], af, bfr[nt]);
            }
        }
        // ---- phase 1: store A seg0, fetch A seg1 ----
        if (pf) {
            *(uint4*)&ASM(d, arow0, aseg) = p0;
            *(uint4*)&ASM(d, arow1, aseg) = p1;
            p0 = *(const uint4*)(Ab0 + knA + 32);
            p1 = *(const uint4*)(Ab1 + knA + 32);
        }
        // ks 1
        {
            const int kc = 16;
            uint32_t bfr[4][2];
#pragma unroll
            for (int nt = 0; nt < 4; nt++) {
                int rb = wn * 32 + nt * 8 + g;
                bfr[nt][0] = *(const uint32_t*)&BSM(s, rb, kc + tig * 2);
                bfr[nt][1] = *(const uint32_t*)&BSM(s, rb, kc + tig * 2 + 8);
            }
#pragma unroll
            for (int mt = 0; mt < 4; mt++) {
                uint32_t af[4];
                int r = wm * 64 + mt * 16 + g;
                af[0] = *(const uint32_t*)&ASM(s, r,     kc + tig * 2);
                af[1] = *(const uint32_t*)&ASM(s, r + 8, kc + tig * 2);
                af[2] = *(const uint32_t*)&ASM(s, r,     kc + tig * 2 + 8);
                af[3] = *(const uint32_t*)&ASM(s, r + 8, kc + tig * 2 + 8);
#pragma unroll
                for (int nt = 0; nt < 4; nt++)
                    mma16816(acc[mt][nt], af, bfr[nt]);
            }
        }
        // ---- phase 2: store A seg1, fetch B seg0 ----
        if (pf) {
            *(uint4*)&ASM(d, arow0, aseg + 32) = p0;
            *(uint4*)&ASM(d, arow1, aseg + 32) = p1;
            p0 = *(const uint4*)(Bb0 + knB);
            p1 = *(const uint4*)(Bb1 + knB);
        }
        // ks 2
        {
            const int kc = 32;
            uint32_t bfr[4][2];
#pragma unroll
            for (int nt = 0; nt < 4; nt++) {
                int rb = wn * 32 + nt * 8 + g;
                bfr[nt][0] = *(const uint32_t*)&BSM(s, rb, kc + tig * 2);
                bfr[nt][1] = *(const uint32_t*)&BSM(s, rb, kc + tig * 2 + 8);
            }
#pragma unroll
            for (int mt = 0; mt < 4; mt++) {
                uint32_t af[4];
                int r = wm * 64 + mt * 16 + g;
                af[0] = *(const uint32_t*)&ASM(s, r,     kc + tig * 2);
                af[1] = *(const uint32_t*)&ASM(s, r + 8, kc + tig * 2);
                af[2] = *(const uint32_t*)&ASM(s, r,     kc + tig * 2 + 8);
                af[3] = *(const uint32_t*)&ASM(s, r + 8, kc + tig * 2 + 8);
#pragma unroll
                for (int nt = 0; nt < 4; nt++)
                    mma16816(acc[mt][nt], af, bfr[nt]);
            }
        }
        // ---- phase 3: store B seg0, fetch B seg1 ----
        if (pf) {
            *(uint4*)&BSM(d, arow0, aseg) = p0;
            *(uint4*)&BSM(d, arow1, aseg) = p1;
            p0 = *(const uint4*)(Bb0 + knB + 32);
            p1 = *(const uint4*)(Bb1 + knB + 32);
        }
        // ks 3
        {
            const int kc = 48;
            uint32_t bfr[4][2];
#pragma unroll
            for (int nt = 0; nt < 4; nt++) {
                int rb = wn * 32 + nt * 8 + g;
                bfr[nt][0] = *(const uint32_t*)&BSM(s, rb, kc + tig * 2);
                bfr[nt][1] = *(const uint32_t*)&BSM(s, rb, kc + tig * 2 + 8);
            }
#pragma unroll
            for (int mt = 0; mt < 4; mt++) {
                uint32_t af[4];
                int r = wm * 64 + mt * 16 + g;
                af[0] = *(const uint32_t*)&ASM(s, r,     kc + tig * 2);
                af[1] = *(const uint32_t*)&ASM(s, r + 8, kc + tig * 2);
                af[2] = *(const uint32_t*)&ASM(s, r,     kc + tig * 2 + 8);
                af[3] = *(const uint32_t*)&ASM(s, r + 8, kc + tig * 2 + 8);
#pragma unroll
                for (int nt = 0; nt < 4; nt++)
                    mma16816(acc[mt][nt], af, bfr[nt]);
            }
        }
        // ---- store B seg1 ----
        if (pf) {
            *(uint4*)&BSM(d, arow0, aseg + 32) = p0;
            *(uint4*)&BSM(d, arow1, aseg + 32) = p1;
        }
        __syncthreads();
    }
#undef ASM
#undef BSM

    // ---------------- epilogue ----------------
#pragma unroll
    for (int mt = 0; mt < 4; mt++) {
#pragma unroll
        for (int half = 0; half < 2; half++) {
            int ml = wm * 64 + mt * 16 + g + half * 8;   // local row 0..127
            int m = m0 + ml;
            if (m >= cnt) continue;
            if (MODE == 0) {
                float wt = wt_s[ml];
                __nv_bfloat16* dst = g_acat + (size_t)(base + m) * K2;
#pragma unroll
                for (int nt = 0; nt < 4; nt++) {
                    int n = n0 + wn * 32 + nt * 8 + tig * 2;
                    float h0 = acc[mt][nt][half * 2 + 0];
                    float h1 = acc[mt][nt][half * 2 + 1];
                    float a0 = (h0 > 0.0f) ? wt * h0 * h0 : 0.0f;
                    float a1 = (h1 > 0.0f) ? wt * h1 * h1 : 0.0f;
                    __nv_bfloat16 hi0 = __float2bfloat16(a0);
                    __nv_bfloat16 hi1 = __float2bfloat16(a1);
                    __nv_bfloat16 lo0 = __float2bfloat16(a0 - __bfloat162float(hi0));
                    __nv_bfloat16 lo1 = __float2bfloat16(a1 - __bfloat162float(hi1));
                    __nv_bfloat162 hh; hh.x = hi0; hh.y = hi1;
                    __nv_bfloat162 ll; ll.x = lo0; ll.y = lo1;
                    *(__nv_bfloat162*)(dst + n)        = hh;
                    *(__nv_bfloat162*)(dst + 1024 + n) = ll;
                }
            } else {
                int tok = tok_s[ml];
                float* orow = out + (size_t)tok * D_DIM;
#pragma unroll
                for (int nt = 0; nt < 4; nt++) {
                    int n = n0 + wn * 32 + nt * 8 + tig * 2;
                    atomicAdd(&orow[n],     acc[mt][nt][half * 2 + 0]);
                    atomicAdd(&orow[n + 1], acc[mt][nt][half * 2 + 1]);
                }
            }
        }
    }
}

// ---------------- launch ------------------------------------------------------
extern "C" void kernel_launch(void* const* d_in, const int* in_sizes, int n_in,
                              void* d_out, int out_size) {
    const float* x  = (const float*)d_in[0];   // [2,2048,1024]
    const float* rw = (const float*)d_in[1];   // [8,1024]
    const float* w1 = (const float*)d_in[2];   // [1024, 8192]
    const float* w2 = (const float*)d_in[3];   // [8192, 1024]
    float* out = (float*)d_out;

    zcnt_kernel<<<1, 32>>>();
    pre_x<<<T_TOK, 128>>>(x, rw, out);

    dim3 tg(32, 32, 16), tb(32, 8);
    convert_w<<<tg, tb>>>(w1, w2);

    cudaFuncSetAttribute(moe_gemm<0>, cudaFuncAttributeMaxDynamicSharedMemorySize, SM_BYTES);
    cudaFuncSetAttribute(moe_gemm<1>, cudaFuncAttributeMaxDynamicSharedMemorySize, SM_BYTES);

    dim3 gup(W_DIM / BN, T_TOK / BM, E_NUM);   // (8, 32, 8)
    moe_gemm<0><<<gup, 256, SM_BYTES>>>(out);
    dim3 gdn(D_DIM / BN, T_TOK / BM, E_NUM);   // (8, 32, 8)
    moe_gemm<1><<<gdn, 256, SM_BYTES>>>(out);
}

// round 15
// speedup vs baseline: 1.2228x; 1.0002x over previous
#include <cuda_runtime.h>
#include <cuda_bf16.h>
#include <math.h>
#include <stdint.h>

// ---------------- problem constants ----------------------------------------
#define T_TOK 4096
#define D_DIM 1024
#define E_NUM 8
#define W_DIM 1024
#define CAP   4096          // per-expert slot capacity (overflow-proof)
#define K3    3072          // weights/x: A=[hi|hi|lo], B=[hi|lo|hi] concatenated
#define K2    2048          // activations: [hi|lo] stored, chunk-remapped on read
#define BK    64
#define NCH   (K3 / BK)     // 48
#define SAS   72            // smem row stride (bf16), BK=64 + pad
#define BM    128
#define BN    128
#define NTILE 8             // n-tiles per (e,my) in both GEMMs (1024/128)
#define TILES 2048          // 32 mtiles x 8 experts x 8 ntiles per phase
#define NWORK 296           // persistent CTAs (148 SMs x 2)

// dynamic smem layout (bytes)
#define OP_ST    (128 * SAS * 2)             // 18432 per operand per stage
#define A_OFF(s) ((s) * OP_ST)
#define B_OFF(s) (2 * OP_ST + (s) * OP_ST)
#define TOK_OFF  (4 * OP_ST)                 // 73728
#define WT_OFF   (TOK_OFF + 512)
#define IDX_OFF  (TOK_OFF + 1024)
#define SM_BYTES (TOK_OFF + 1040)            // 74768 (x2 = 149.5 KB < 228 KB)

// ---------------- device scratch --------------------------------------------
__device__ int   g_fill[E_NUM];
__device__ int   g_q0, g_q1;
__device__ int   g_done[E_NUM * 32];         // per (e,my) up-proj tile countdown
__device__ int   g_tok [E_NUM * CAP];
__device__ float g_wt  [E_NUM * CAP];
__device__ __nv_bfloat16 g_xcat [(size_t)T_TOK * K3];
__device__ __nv_bfloat16 g_w1cat[(size_t)E_NUM * W_DIM * K3];
__device__ __nv_bfloat16 g_w2cat[(size_t)E_NUM * D_DIM * K3];
__device__ __nv_bfloat16 g_acat [(size_t)E_NUM * CAP * K2];

// 64-wide chunk -> stored-K offset for deduped activations ([hi|hi|lo] read)
__device__ __forceinline__ int kbA64(int c) {
    return (c < 16) ? c * 64 : (c < 32 ? (c - 16) * 64 : (c - 32) * 64 + 1024);
}

// ---------------- pre-pass ---------------------------------------------------
__global__ void zcnt_kernel() {
    int i = threadIdx.x;
    if (i < E_NUM) g_fill[i] = 0;
    if (i < E_NUM * 32) g_done[i] = 0;
    if (i == 0) { g_q0 = 0; g_q1 = 0; }
}

// fused: zero out + x split + router + slot assignment
__global__ void __launch_bounds__(128) pre_x(const float* __restrict__ x,
                                             const float* __restrict__ rw,
                                             float* __restrict__ out) {
    __shared__ float wsum[4][E_NUM];
    int t = blockIdx.x;
    int tid = threadIdx.x, lane = tid & 31, wrp = tid >> 5;
    const float* xr = x + (size_t)t * D_DIM;
    int d0 = tid * 8;

    float4 v0 = *(const float4*)(xr + d0);
    float4 v1 = *(const float4*)(xr + d0 + 4);
    float xv[8] = { v0.x, v0.y, v0.z, v0.w, v1.x, v1.y, v1.z, v1.w };

    float4 z = make_float4(0.f, 0.f, 0.f, 0.f);
    *(float4*)(out + (size_t)t * D_DIM + d0)     = z;
    *(float4*)(out + (size_t)t * D_DIM + d0 + 4) = z;

    size_t b = (size_t)t * K3;
    __nv_bfloat16 hi8[8], lo8[8];
#pragma unroll
    for (int i = 0; i < 8; i++) {
        hi8[i] = __float2bfloat16(xv[i]);
        lo8[i] = __float2bfloat16(xv[i] - __bfloat162float(hi8[i]));
    }
    *(uint4*)(&g_xcat[b + d0])        = *(uint4*)hi8;
    *(uint4*)(&g_xcat[b + 1024 + d0]) = *(uint4*)hi8;
    *(uint4*)(&g_xcat[b + 2048 + d0]) = *(uint4*)lo8;

    float p[E_NUM];
#pragma unroll
    for (int e = 0; e < E_NUM; e++) {
        const float* wr = rw + e * D_DIM + d0;
        float s = 0.f;
#pragma unroll
        for (int i = 0; i < 8; i++) s += xv[i] * wr[i];
        p[e] = s;
    }
#pragma unroll
    for (int e = 0; e < E_NUM; e++)
#pragma unroll
        for (int o = 16; o; o >>= 1) p[e] += __shfl_xor_sync(0xffffffffu, p[e], o);
    if (lane == 0)
#pragma unroll
        for (int e = 0; e < E_NUM; e++) wsum[wrp][e] = p[e];
    __syncthreads();
    if (tid == 0) {
        float q[E_NUM];
#pragma unroll
        for (int e = 0; e < E_NUM; e++)
            q[e] = wsum[0][e] + wsum[1][e] + wsum[2][e] + wsum[3][e];
        int i1 = 0; float v1 = q[0];
#pragma unroll
        for (int e = 1; e < E_NUM; e++) if (q[e] > v1) { v1 = q[e]; i1 = e; }
        int i2 = -1; float v2 = -3.0e38f;
#pragma unroll
        for (int e = 0; e < E_NUM; e++) if (e != i1 && q[e] > v2) { v2 = q[e]; i2 = e; }
        float p1 = 1.0f / (1.0f + expf(-v1));
        float p2 = 1.0f / (1.0f + expf(-v2));
        float s = p1 + p2 + 1e-20f;
        int pos1 = atomicAdd(&g_fill[i1], 1);
        g_tok[i1 * CAP + pos1] = t;
        g_wt [i1 * CAP + pos1] = p1 / s;
        int pos2 = atomicAdd(&g_fill[i2], 1);
        g_tok[i2 * CAP + pos2] = t;
        g_wt [i2 * CAP + pos2] = p2 / s;
    }
}

// Per-expert 1024x1024 transpose + split: dst[e][n][k-seg], segs [hi|lo|hi]
__global__ void convert_w(const float* __restrict__ w1, const float* __restrict__ w2) {
    __shared__ float tile[32][33];
    int sel = blockIdx.z >> 3;
    int e   = blockIdx.z & 7;
    int r0 = blockIdx.y * 32, c0 = blockIdx.x * 32;
    const float* src = sel ? w2 : w1;
    int src_ld  = sel ? 1024 : 8192;
    int row_off = sel ? e * 1024 : 0;
    int col_off = sel ? 0 : e * 1024;
    const float* s = src + (size_t)(row_off + r0) * src_ld + col_off + c0;
#pragma unroll
    for (int i = threadIdx.y; i < 32; i += 8)
        tile[i][threadIdx.x] = s[(size_t)i * src_ld + threadIdx.x];
    __syncthreads();
    __nv_bfloat16* d = (sel ? g_w2cat : g_w1cat) + (size_t)e * 1024 * K3;
#pragma unroll
    for (int i = threadIdx.y; i < 32; i += 8) {
        int c = c0 + i;
        int r = r0 + threadIdx.x;
        float v = tile[threadIdx.x][i];
        __nv_bfloat16 hi = __float2bfloat16(v);
        __nv_bfloat16 lo = __float2bfloat16(v - __bfloat162float(hi));
        size_t bi = (size_t)c * K3 + r;
        d[bi] = hi; d[bi + 1024] = lo; d[bi + 2048] = hi;
    }
}

// ---------------- mma.sync helper -------------------------------------------
__device__ __forceinline__ void mma16816(float* d, const uint32_t* a, const uint32_t* b) {
    asm volatile(
        "mma.sync.aligned.m16n8k16.row.col.f32.bf16.bf16.f32 "
        "{%0,%1,%2,%3}, {%4,%5,%6,%7}, {%8,%9}, {%0,%1,%2,%3};"
        : "+f"(d[0]), "+f"(d[1]), "+f"(d[2]), "+f"(d[3])
        : "r"(a[0]), "r"(a[1]), "r"(a[2]), "r"(a[3]), "r"(b[0]), "r"(b[1]));
}

// ---------------- fused persistent grouped GEMM ------------------------------
// phase 0: up-proj  (A = g_xcat [K3] by token, B = g_w1cat, epi -> g_acat [hi|lo])
// phase 1: down-proj(A = g_acat [K2] remapped,  B = g_w2cat, epi -> atomicAdd out)
// tile idx (my-major): idx = my*64 + e*8 + nx
__global__ void __launch_bounds__(256, 2) moe_fused(float* __restrict__ out) {
    extern __shared__ char sm[];
    int*   tok_s = (int*)  (sm + TOK_OFF);
    float* wt_s  = (float*)(sm + WT_OFF);
    int*   idx_s = (int*)  (sm + IDX_OFF);

    int tid = threadIdx.x, lane = tid & 31, wid = tid >> 5;
    int wm = wid & 1, wn = wid >> 1;
    int g = lane >> 2, tig = lane & 3;

#define ASM(s, r, c) (*(__nv_bfloat16*)(sm + A_OFF(s) + ((r) * SAS + (c)) * 2))
#define BSM(s, r, c) (*(__nv_bfloat16*)(sm + B_OFF(s) + ((r) * SAS + (c)) * 2))

#pragma unroll 1
    for (int phase = 0; phase < 2; phase++) {
#pragma unroll 1
        while (true) {
            if (tid == 0)
                idx_s[0] = atomicAdd(phase ? &g_q1 : &g_q0, 1);
            __syncthreads();                 // also separates prev tile's epilogue
            int idx = idx_s[0];
            if (idx >= TILES) break;
            int my = idx >> 6;
            int e  = (idx >> 3) & 7;
            int nx = idx & 7;
            int cnt = g_fill[e];
            int m0 = my * BM;
            if (m0 >= cnt) continue;
            int base = e * CAP;
            int n0 = nx * BN;

            // phase-1 dependency: all 8 up-tiles of (e,my) must be complete
            if (phase == 1) {
                if (tid == 0) {
                    while (atomicAdd(&g_done[e * 32 + my], 0) < NTILE)
                        __nanosleep(128);
                }
                __syncthreads();
                __threadfence();             // acquire: order acat reads after flag
            }

            if (tid < 128) {
                int m = m0 + tid;
                tok_s[tid] = (m < cnt) ? g_tok[base + m] : 0;
                wt_s [tid] = (m < cnt) ? g_wt [base + m] : 0.0f;
            }
            __syncthreads();

            int arow0 = tid >> 2, arow1 = arow0 + 64;
            int aseg  = (tid & 3) * 8;
            const __nv_bfloat16 *Ab0, *Ab1;
            if (phase == 0) {
                Ab0 = g_xcat + (size_t)tok_s[arow0] * K3 + aseg;
                Ab1 = g_xcat + (size_t)tok_s[arow1] * K3 + aseg;
            } else {
                Ab0 = g_acat + (size_t)(base + m0 + arow0) * K2 + aseg;
                Ab1 = g_acat + (size_t)(base + m0 + arow1) * K2 + aseg;
            }
            const __nv_bfloat16* Bexp = (phase ? g_w2cat : g_w1cat) + (size_t)e * 1024 * K3;
            const __nv_bfloat16* Bb0 = Bexp + (size_t)(n0 + arow0) * K3 + aseg;
            const __nv_bfloat16* Bb1 = Bexp + (size_t)(n0 + arow1) * K3 + aseg;

            float acc[4][4][4];
#pragma unroll
            for (int i = 0; i < 4; i++)
#pragma unroll
                for (int j = 0; j < 4; j++)
#pragma unroll
                    for (int q = 0; q < 4; q++) acc[i][j][q] = 0.0f;

            // prologue: chunk 0 -> stage 0
            *(uint4*)&ASM(0, arow0, aseg)      = *(const uint4*)(Ab0);
            *(uint4*)&ASM(0, arow1, aseg)      = *(const uint4*)(Ab1);
            *(uint4*)&ASM(0, arow0, aseg + 32) = *(const uint4*)(Ab0 + 32);
            *(uint4*)&ASM(0, arow1, aseg + 32) = *(const uint4*)(Ab1 + 32);
            *(uint4*)&BSM(0, arow0, aseg)      = *(const uint4*)(Bb0);
            *(uint4*)&BSM(0, arow1, aseg)      = *(const uint4*)(Bb1);
            *(uint4*)&BSM(0, arow0, aseg + 32) = *(const uint4*)(Bb0 + 32);
            *(uint4*)&BSM(0, arow1, aseg + 32) = *(const uint4*)(Bb1 + 32);
            __syncthreads();

#pragma unroll 1
            for (int c = 0; c < NCH; c++) {
                int s = c & 1;
                int d = s ^ 1;
                bool pf = (c + 1 < NCH);
                int knB = (c + 1) * BK;
                int knA = phase ? kbA64(c + 1) : knB;

                uint4 p0, p1;
                if (pf) { p0 = *(const uint4*)(Ab0 + knA); p1 = *(const uint4*)(Ab1 + knA); }
#pragma unroll
                for (int ks = 0; ks < 4; ks++) {
                    const int kc = ks * 16;
                    uint32_t bfr[4][2];
#pragma unroll
                    for (int nt = 0; nt < 4; nt++) {
                        int rb = wn * 32 + nt * 8 + g;
                        bfr[nt][0] = *(const uint32_t*)&BSM(s, rb, kc + tig * 2);
                        bfr[nt][1] = *(const uint32_t*)&BSM(s, rb, kc + tig * 2 + 8);
                    }
#pragma unroll
                    for (int mt = 0; mt < 4; mt++) {
                        uint32_t af[4];
                        int r = wm * 64 + mt * 16 + g;
                        af[0] = *(const uint32_t*)&ASM(s, r,     kc + tig * 2);
                        af[1] = *(const uint32_t*)&ASM(s, r + 8, kc + tig * 2);
                        af[2] = *(const uint32_t*)&ASM(s, r,     kc + tig * 2 + 8);
                        af[3] = *(const uint32_t*)&ASM(s, r + 8, kc + tig * 2 + 8);
#pragma unroll
                        for (int nt = 0; nt < 4; nt++)
                            mma16816(acc[mt][nt], af, bfr[nt]);
                    }
                    // staged prefetch: store prev batch, fetch next (peak 8 regs)
                    if (pf) {
                        if (ks == 0) {
                            *(uint4*)&ASM(d, arow0, aseg) = p0;
                            *(uint4*)&ASM(d, arow1, aseg) = p1;
                            p0 = *(const uint4*)(Ab0 + knA + 32);
                            p1 = *(const uint4*)(Ab1 + knA + 32);
                        } else if (ks == 1) {
                            *(uint4*)&ASM(d, arow0, aseg + 32) = p0;
                            *(uint4*)&ASM(d, arow1, aseg + 32) = p1;
                            p0 = *(const uint4*)(Bb0 + knB);
                            p1 = *(const uint4*)(Bb1 + knB);
                        } else if (ks == 2) {
                            *(uint4*)&BSM(d, arow0, aseg) = p0;
                            *(uint4*)&BSM(d, arow1, aseg) = p1;
                            p0 = *(const uint4*)(Bb0 + knB + 32);
                            p1 = *(const uint4*)(Bb1 + knB + 32);
                        } else {
                            *(uint4*)&BSM(d, arow0, aseg + 32) = p0;
                            *(uint4*)&BSM(d, arow1, aseg + 32) = p1;
                        }
                    }
                }
                __syncthreads();
            }

            // ---------------- epilogue ----------------
#pragma unroll
            for (int mt = 0; mt < 4; mt++) {
#pragma unroll
                for (int half = 0; half < 2; half++) {
                    int ml = wm * 64 + mt * 16 + g + half * 8;
                    int m = m0 + ml;
                    if (m >= cnt) continue;
                    if (phase == 0) {
                        float wt = wt_s[ml];
                        __nv_bfloat16* dst = g_acat + (size_t)(base + m) * K2;
#pragma unroll
                        for (int nt = 0; nt < 4; nt++) {
                            int n = n0 + wn * 32 + nt * 8 + tig * 2;
                            float h0 = acc[mt][nt][half * 2 + 0];
                            float h1 = acc[mt][nt][half * 2 + 1];
                            float a0 = (h0 > 0.0f) ? wt * h0 * h0 : 0.0f;
                            float a1 = (h1 > 0.0f) ? wt * h1 * h1 : 0.0f;
                            __nv_bfloat16 hi0 = __float2bfloat16(a0);
                            __nv_bfloat16 hi1 = __float2bfloat16(a1);
                            __nv_bfloat16 lo0 = __float2bfloat16(a0 - __bfloat162float(hi0));
                            __nv_bfloat16 lo1 = __float2bfloat16(a1 - __bfloat162float(hi1));
                            __nv_bfloat162 hh; hh.x = hi0; hh.y = hi1;
                            __nv_bfloat162 ll; ll.x = lo0; ll.y = lo1;
                            *(__nv_bfloat162*)(dst + n)        = hh;
                            *(__nv_bfloat162*)(dst + 1024 + n) = ll;
                        }
                    } else {
                        int tok = tok_s[ml];
                        float* orow = out + (size_t)tok * D_DIM;
#pragma unroll
                        for (int nt = 0; nt < 4; nt++) {
                            int n = n0 + wn * 32 + nt * 8 + tig * 2;
                            atomicAdd(&orow[n],     acc[mt][nt][half * 2 + 0]);
                            atomicAdd(&orow[n + 1], acc[mt][nt][half * 2 + 1]);
                        }
                    }
                }
            }

            // phase-0 completion: release acat writes, bump (e,my) counter
            if (phase == 0) {
                __threadfence();
                __syncthreads();
                if (tid == 0) atomicAdd(&g_done[e * 32 + my], 1);
            }
        }
    }
#undef ASM
#undef BSM
}

// ---------------- launch ------------------------------------------------------
extern "C" void kernel_launch(void* const* d_in, const int* in_sizes, int n_in,
                              void* d_out, int out_size) {
    const float* x  = (const float*)d_in[0];   // [2,2048,1024]
    const float* rw = (const float*)d_in[1];   // [8,1024]
    const float* w1 = (const float*)d_in[2];   // [1024, 8192]
    const float* w2 = (const float*)d_in[3];   // [8192, 1024]
    float* out = (float*)d_out;

    zcnt_kernel<<<1, 256>>>();
    pre_x<<<T_TOK, 128>>>(x, rw, out);

    dim3 tg(32, 32, 16), tb(32, 8);
    convert_w<<<tg, tb>>>(w1, w2);

    cudaFuncSetAttribute(moe_fused, cudaFuncAttributeMaxDynamicSharedMemorySize, SM_BYTES);
    moe_fused<<<NWORK, 256, SM_BYTES>>>(out);
}